// round 1
// baseline (speedup 1.0000x reference)
#include <cuda_runtime.h>
#include <cuda_bf16.h>

// RPDC depthwise 5x5 conv (built from 8 taps of a 3x3 weight).
// x: (16,256,128,128) f32, weight: (256,1,3,3) f32, out: (16,256,128,128) f32.
//
// K[5][5] layout (cross-correlation, pad=2):
//   +tap[j] at POS = (0,0),(0,2),(0,4),(2,0),(2,4),(4,0),(4,2),(4,4)
//   -tap[j] at NEG = (1,1),(1,2),(1,3),(2,1),(2,3),(3,1),(3,2),(3,3)
// tap[j] = weight[c][0][ (j+1)/3 ][ (j+1)%3 ]  (i.e. flattened 3x3 indices 1..8)

#define W_DIM 128
#define H_DIM 128
#define TILE_H 32
#define SMEM_W 132   // 128 + 2*2 halo, stride 132 floats (132 % 32 = 4 -> conflict free)

__global__ __launch_bounds__(128) void rpdc_kernel(
    const float* __restrict__ x,
    const float* __restrict__ w,
    float* __restrict__ out)
{
    __shared__ float s[TILE_H + 4][SMEM_W];

    const int tx    = threadIdx.x;            // column 0..127
    const int tile  = blockIdx.x;             // 0..3 (row tile within plane)
    const int plane = blockIdx.y;             // n*256 + c, 0..4095
    const int c     = plane & 255;

    const float* xp = x + (size_t)plane * (H_DIM * W_DIM);
    float*       op = out + (size_t)plane * (H_DIM * W_DIM);
    const int y0 = tile * TILE_H;

    // --- taps (broadcast load, hits constant/L1) ---
    const float* wp = w + c * 9;
    const float t0 = wp[1], t1 = wp[2], t2 = wp[3], t3 = wp[4];
    const float t4 = wp[5], t5 = wp[6], t6 = wp[7], t7 = wp[8];

    // --- load tile + vertical halo into smem (fully coalesced) ---
    #pragma unroll
    for (int r = 0; r < TILE_H + 4; ++r) {
        int gy = y0 + r - 2;
        float v = (gy >= 0 && gy < H_DIM) ? xp[gy * W_DIM + tx] : 0.0f;
        s[r][tx + 2] = v;
    }
    // zero the 4 halo columns (padding)
    if (tx < 4) {
        int col = (tx < 2) ? tx : tx + 128;   // 0,1,130,131
        #pragma unroll
        for (int r = 0; r < TILE_H + 4; ++r) s[r][col] = 0.0f;
    }
    __syncthreads();

    // --- rolling 5x5 register window: 5 LDS per output row instead of 16 ---
    float win[5][5];
    #pragma unroll
    for (int r = 0; r < 4; ++r) {
        #pragma unroll
        for (int cc = 0; cc < 5; ++cc) win[r + 1][cc] = s[r][tx + cc];
    }

    #pragma unroll
    for (int ry = 0; ry < TILE_H; ++ry) {
        // shift window up
        #pragma unroll
        for (int r = 0; r < 4; ++r) {
            #pragma unroll
            for (int cc = 0; cc < 5; ++cc) win[r][cc] = win[r + 1][cc];
        }
        // load new bottom row
        #pragma unroll
        for (int cc = 0; cc < 5; ++cc) win[4][cc] = s[ry + 4][tx + cc];

        float acc;
        acc  = t0 * (win[0][0] - win[1][1]);
        acc += t1 * (win[0][2] - win[1][2]);
        acc += t2 * (win[0][4] - win[1][3]);
        acc += t3 * (win[2][0] - win[2][1]);
        acc += t4 * (win[2][4] - win[2][3]);
        acc += t5 * (win[4][0] - win[3][1]);
        acc += t6 * (win[4][2] - win[3][2]);
        acc += t7 * (win[4][4] - win[3][3]);

        op[(y0 + ry) * W_DIM + tx] = acc;
    }
}

extern "C" void kernel_launch(void* const* d_in, const int* in_sizes, int n_in,
                              void* d_out, int out_size)
{
    const float* x = (const float*)d_in[0];   // 16*256*128*128
    const float* w = (const float*)d_in[1];   // 256*1*3*3
    float* out = (float*)d_out;

    dim3 grid(H_DIM / TILE_H, 16 * 256);      // (4, 4096)
    rpdc_kernel<<<grid, 128>>>(x, w, out);
}